// round 4
// baseline (speedup 1.0000x reference)
#include <cuda_runtime.h>
#include <cuda_bf16.h>
#include <math.h>

// Problem shape (fixed by reference setup_inputs)
#define BB 4
#define TT 8192
#define DD 1024
#define LL 64             // timesteps per chunk
#define CC 128            // chunks per sequence (LL*CC == TT)
#define VEC 4             // d-columns per thread in bulk kernels
#define NTH (DD / VEC)    // 256 threads per bulk block

// kernel-2 tiling: each block scans CC chunks for DT d-columns
#define DT 8              // d-columns per scan block
#define K2_NTH (CC * DT)  // 1024 threads

// Scratch: chunk end-states and carry-in states, [B, C, D] of (re,im).
// (no cudaMalloc allowed -> __device__ globals; 4 MB each)
__device__ float2 g_e[BB * CC * DD];
__device__ float2 g_c[BB * CC * DD];

// Per-d multiplier z = e^{-|a|} * cis(w), computed in double then rounded.
// Setup-only FP64: off the hot path.
__device__ __forceinline__ void make_z(float dec, float frq, float& zr, float& zi)
{
    const double a = fabs((double)dec);
    const double w = (double)frq;
    const double r = exp(-a);
    zr = (float)(r * cos(w));
    zi = (float)(r * sin(w));
}

// ---------------------------------------------------------------------------
// Kernel 1: local scan per chunk with zero initial state; store end states.
// grid = (CC, BB), block = 256 threads; thread handles 4 consecutive d.
// ---------------------------------------------------------------------------
__global__ void __launch_bounds__(NTH) k_local_scan(
    const float* __restrict__ x,
    const float* __restrict__ decay,
    const float* __restrict__ freq)
{
    const int d0 = threadIdx.x * VEC;
    const int c  = blockIdx.x;
    const int b  = blockIdx.y;

    const float4 dec = *(const float4*)(decay + d0);
    const float4 frq = *(const float4*)(freq  + d0);

    float zr[VEC], zi[VEC], hr[VEC], hi[VEC];
    make_z(dec.x, frq.x, zr[0], zi[0]);
    make_z(dec.y, frq.y, zr[1], zi[1]);
    make_z(dec.z, frq.z, zr[2], zi[2]);
    make_z(dec.w, frq.w, zr[3], zi[3]);
#pragma unroll
    for (int v = 0; v < VEC; ++v) { hr[v] = 0.0f; hi[v] = 0.0f; }

    const float4* xp = (const float4*)(x + ((size_t)b * TT + (size_t)c * LL) * DD + d0);
    const int stride4 = DD / 4;   // float4 stride per timestep

#pragma unroll 4
    for (int j = 0; j < LL; ++j) {
        const float4 xv = xp[(size_t)j * stride4];
        const float xs[VEC] = {xv.x, xv.y, xv.z, xv.w};
#pragma unroll
        for (int v = 0; v < VEC; ++v) {
            const float nr = fmaf(zr[v], hr[v], fmaf(-zi[v], hi[v], xs[v]));
            const float ni = fmaf(zi[v], hr[v], zr[v] * hi[v]);
            hr[v] = nr; hi[v] = ni;
        }
    }

    float2* ep = g_e + ((size_t)b * CC + c) * DD + d0;
    ((float4*)ep)[0] = make_float4(hr[0], hi[0], hr[1], hi[1]);
    ((float4*)ep)[1] = make_float4(hr[2], hi[2], hr[3], hi[3]);
}

// ---------------------------------------------------------------------------
// Kernel 2: Kogge-Stone scan over chunks.
// H_c = A * H_{c-1} + e_c with A = z^L (constant per d).
// Inclusive prefix computed in log2(CC)=7 steps; at offset o = 2^s,
// h_c += A^o * h_{c-o}. A^o chain kept in DOUBLE (exact squarings),
// rounded to float for the fp32 FMAs. Carry-in for chunk c is H_{c-1}.
// grid = (DD/DT, BB), block = 1024 threads; tid -> (c = tid/DT, dl = tid%DT).
// ---------------------------------------------------------------------------
__global__ void __launch_bounds__(K2_NTH) k_carry_scan(
    const float* __restrict__ decay,
    const float* __restrict__ freq)
{
    __shared__ float2 s[CC * DT];

    const int tid = threadIdx.x;
    const int dl  = tid % DT;
    const int c   = tid / DT;
    const int d   = blockIdx.x * DT + dl;
    const int b   = blockIdx.y;

    // A = z^L in closed form, double precision
    const double a = fabs((double)decay[d]);
    const double w = (double)freq[d];
    const double rL  = exp(-a * (double)LL);
    const double phi = w * (double)LL;
    double Ar = rL * cos(phi);
    double Ai = rL * sin(phi);

    const size_t base = ((size_t)b * CC + c) * DD + d;
    float2 h = g_e[base];
    s[c * DT + dl] = h;
    __syncthreads();

#pragma unroll
    for (int o = 1; o < CC; o <<= 1) {
        float2 p = make_float2(0.0f, 0.0f);
        if (c >= o) p = s[(c - o) * DT + dl];
        __syncthreads();
        const float fAr = (float)Ar, fAi = (float)Ai;
        // h += A^o * p   (complex)
        h.x = fmaf(fAr, p.x, fmaf(-fAi, p.y, h.x));
        h.y = fmaf(fAi, p.x, fmaf( fAr, p.y, h.y));
        s[c * DT + dl] = h;
        // A^o -> A^(2o)  (exact in double)
        const double nAr = Ar * Ar - Ai * Ai;
        const double nAi = 2.0 * Ar * Ai;
        Ar = nAr; Ai = nAi;
        __syncthreads();
    }

    // carry-in for chunk c = inclusive prefix of chunk c-1
    float2 carry = (c == 0) ? make_float2(0.0f, 0.0f) : s[(c - 1) * DT + dl];
    g_c[base] = carry;
}

// ---------------------------------------------------------------------------
// Kernel 3: final scan per chunk seeded with carry; write y = Re(h).
// Chunk order reversed (c = CC-1-blockIdx.x) so the tail of x — still
// L2-resident after kernel 1 — is re-read first (L2 hits).
// grid = (CC, BB), block = 256; thread handles 4 consecutive d.
// ---------------------------------------------------------------------------
__global__ void __launch_bounds__(NTH) k_final_scan(
    const float* __restrict__ x,
    const float* __restrict__ decay,
    const float* __restrict__ freq,
    float* __restrict__ y)
{
    const int d0 = threadIdx.x * VEC;
    const int c  = CC - 1 - blockIdx.x;
    const int b  = blockIdx.y;

    const float4 dec = *(const float4*)(decay + d0);
    const float4 frq = *(const float4*)(freq  + d0);

    float zr[VEC], zi[VEC], hr[VEC], hi[VEC];
    make_z(dec.x, frq.x, zr[0], zi[0]);
    make_z(dec.y, frq.y, zr[1], zi[1]);
    make_z(dec.z, frq.z, zr[2], zi[2]);
    make_z(dec.w, frq.w, zr[3], zi[3]);

    {   // seed with the carry-in state for this chunk
        const float2* cp = g_c + ((size_t)b * CC + c) * DD + d0;
        const float4 c01 = ((const float4*)cp)[0];
        const float4 c23 = ((const float4*)cp)[1];
        hr[0] = c01.x; hi[0] = c01.y; hr[1] = c01.z; hi[1] = c01.w;
        hr[2] = c23.x; hi[2] = c23.y; hr[3] = c23.z; hi[3] = c23.w;
    }

    const size_t off = ((size_t)b * TT + (size_t)c * LL) * DD + d0;
    const float4* xp = (const float4*)(x + off);
    float4*       yp = (float4*)(y + off);
    const int stride4 = DD / 4;

#pragma unroll 4
    for (int j = 0; j < LL; ++j) {
        const float4 xv = xp[(size_t)j * stride4];
        const float xs[VEC] = {xv.x, xv.y, xv.z, xv.w};
#pragma unroll
        for (int v = 0; v < VEC; ++v) {
            const float nr = fmaf(zr[v], hr[v], fmaf(-zi[v], hi[v], xs[v]));
            const float ni = fmaf(zi[v], hr[v], zr[v] * hi[v]);
            hr[v] = nr; hi[v] = ni;
        }
        yp[(size_t)j * stride4] = make_float4(hr[0], hr[1], hr[2], hr[3]);
    }
}

// ---------------------------------------------------------------------------
extern "C" void kernel_launch(void* const* d_in, const int* in_sizes, int n_in,
                              void* d_out, int out_size)
{
    const float* x     = (const float*)d_in[0];
    const float* decay = (const float*)d_in[1];
    const float* freq  = (const float*)d_in[2];
    float* y = (float*)d_out;

    dim3 grid(CC, BB);
    k_local_scan<<<grid, NTH>>>(x, decay, freq);
    k_carry_scan<<<dim3(DD / DT, BB), K2_NTH>>>(decay, freq);
    k_final_scan<<<grid, NTH>>>(x, decay, freq, y);
}

// round 8
// speedup vs baseline: 2.0519x; 2.0519x over previous
#include <cuda_runtime.h>
#include <cuda_bf16.h>
#include <math.h>

// Problem shape (fixed by reference setup_inputs)
#define BB 4
#define TT 8192
#define DD 1024
#define LL 64             // timesteps per chunk
#define CC 128            // chunks per sequence (LL*CC == TT)
#define VEC 4             // d-columns per thread
#define NTH (DD / VEC)    // 256 threads per block

// Scratch (no cudaMalloc -> __device__ globals)
__device__ float2 g_z[DD];              // z = e^{-|a|} cis(w)
__device__ float2 g_A[DD];              // A = z^LL
__device__ float2 g_agg[BB * CC * DD];  // chunk aggregates (4 MB)
__device__ int    g_flag[BB * CC];      // 0 = not ready, 1 = aggregate ready

__device__ __forceinline__ int ld_acq(const int* p) {
    int v;
    asm volatile("ld.acquire.gpu.b32 %0, [%1];" : "=r"(v) : "l"(p));
    return v;
}
__device__ __forceinline__ void st_rel(int* p, int v) {
    asm volatile("st.release.gpu.b32 [%0], %1;" :: "l"(p), "r"(v) : "memory");
}

// ---------------------------------------------------------------------------
// Setup: all transcendentals (double) once per d; also reset flags (runs at
// the start of every graph replay, so flags are always fresh).
// ---------------------------------------------------------------------------
__global__ void __launch_bounds__(DD) k_setup(
    const float* __restrict__ decay,
    const float* __restrict__ freq)
{
    const int d = threadIdx.x;
    const double a = fabs((double)decay[d]);
    const double w = (double)freq[d];
    const double r = exp(-a);
    g_z[d] = make_float2((float)(r * cos(w)), (float)(r * sin(w)));
    const double rL = exp(-a * (double)LL);
    const double ph = w * (double)LL;
    g_A[d] = make_float2((float)(rL * cos(ph)), (float)(rL * sin(ph)));
    if (d < BB * CC) g_flag[d] = 0;
}

// ---------------------------------------------------------------------------
// Fused scan: per CTA (chunk c, batch b):
//  1) local scan of chunk (h=0), producing aggregate e_c
//  2) publish e_c (release flag)
//  3) carry H_{c-1} by Horner walk over predecessors' aggregates:
//       H <- A*H + e_j,  j = 0..c-1   (flags checked in batches of 4)
//  4) rescan chunk seeded with H (x re-read hits L2), write y = Re(h)
// grid = (CC, BB), block = 256; thread owns 4 consecutive d.
// ---------------------------------------------------------------------------
__global__ void __launch_bounds__(NTH) k_scan(
    const float* __restrict__ x,
    float* __restrict__ y)
{
    const int d0 = threadIdx.x * VEC;
    const int c  = blockIdx.x;
    const int b  = blockIdx.y;

    const float4 z01 = ((const float4*)(g_z + d0))[0];   // zr0,zi0,zr1,zi1
    const float4 z23 = ((const float4*)(g_z + d0))[1];
    const float zr[VEC] = {z01.x, z01.z, z23.x, z23.z};
    const float zi[VEC] = {z01.y, z01.w, z23.y, z23.w};
    const float4 A01 = ((const float4*)(g_A + d0))[0];
    const float4 A23 = ((const float4*)(g_A + d0))[1];
    const float Ar[VEC] = {A01.x, A01.z, A23.x, A23.z};
    const float Ai[VEC] = {A01.y, A01.w, A23.y, A23.w};

    const size_t off = ((size_t)b * TT + (size_t)c * LL) * DD + d0;
    const float4* xp = (const float4*)(x + off);
    const int stride4 = DD / 4;

    // ---- Phase 1: local scan (zero initial state) ----
    float er[VEC] = {0.f, 0.f, 0.f, 0.f};
    float ei[VEC] = {0.f, 0.f, 0.f, 0.f};
#pragma unroll 8
    for (int j = 0; j < LL; ++j) {
        const float4 xv = xp[(size_t)j * stride4];
        const float xs[VEC] = {xv.x, xv.y, xv.z, xv.w};
#pragma unroll
        for (int v = 0; v < VEC; ++v) {
            const float nr = fmaf(zr[v], er[v], fmaf(-zi[v], ei[v], xs[v]));
            const float ni = fmaf(zi[v], er[v], zr[v] * ei[v]);
            er[v] = nr; ei[v] = ni;
        }
    }

    // ---- Phase 2: publish aggregate ----
    const int fb = b * CC;
    {
        float2* ap = g_agg + ((size_t)(fb + c)) * DD + d0;
        ((float4*)ap)[0] = make_float4(er[0], ei[0], er[1], ei[1]);
        ((float4*)ap)[1] = make_float4(er[2], ei[2], er[3], ei[3]);
        __threadfence();
        __syncthreads();
        if (threadIdx.x == 0) st_rel(&g_flag[fb + c], 1);
    }

    // ---- Phase 3: carry H_{c-1} via Horner over predecessor aggregates ----
    float Hr[VEC] = {0.f, 0.f, 0.f, 0.f};
    float Hi[VEC] = {0.f, 0.f, 0.f, 0.f};
    for (int jb = 0; jb < c; jb += 4) {
        const int n = (c - jb < 4) ? (c - jb) : 4;
        if (threadIdx.x == 0) {
            for (int k = 0; k < n; ++k)
                while (ld_acq(&g_flag[fb + jb + k]) == 0) __nanosleep(64);
        }
        __syncthreads();   // acquire by tid0 + barrier -> block sees aggregates

        float4 s01[4], s23[4];
        for (int k = 0; k < n; ++k) {
            const float4* sp = (const float4*)(g_agg + ((size_t)(fb + jb + k)) * DD + d0);
            s01[k] = sp[0];
            s23[k] = sp[1];
        }
        for (int k = 0; k < n; ++k) {
            const float sr[VEC] = {s01[k].x, s01[k].z, s23[k].x, s23[k].z};
            const float si[VEC] = {s01[k].y, s01[k].w, s23[k].y, s23[k].w};
#pragma unroll
            for (int v = 0; v < VEC; ++v) {
                const float nr = fmaf(Ar[v], Hr[v], fmaf(-Ai[v], Hi[v], sr[v]));
                const float ni = fmaf(Ai[v], Hr[v], fmaf( Ar[v], Hi[v], si[v]));
                Hr[v] = nr; Hi[v] = ni;
            }
        }
    }

    // ---- Phase 4: final scan seeded with carry; x re-read (L2), write y ----
    float hr[VEC], hi[VEC];
#pragma unroll
    for (int v = 0; v < VEC; ++v) { hr[v] = Hr[v]; hi[v] = Hi[v]; }

    float4* yp = (float4*)(y + off);
#pragma unroll 8
    for (int j = 0; j < LL; ++j) {
        const float4 xv = xp[(size_t)j * stride4];
        const float xs[VEC] = {xv.x, xv.y, xv.z, xv.w};
#pragma unroll
        for (int v = 0; v < VEC; ++v) {
            const float nr = fmaf(zr[v], hr[v], fmaf(-zi[v], hi[v], xs[v]));
            const float ni = fmaf(zi[v], hr[v], zr[v] * hi[v]);
            hr[v] = nr; hi[v] = ni;
        }
        yp[(size_t)j * stride4] = make_float4(hr[0], hr[1], hr[2], hr[3]);
    }
}

// ---------------------------------------------------------------------------
extern "C" void kernel_launch(void* const* d_in, const int* in_sizes, int n_in,
                              void* d_out, int out_size)
{
    const float* x     = (const float*)d_in[0];
    const float* decay = (const float*)d_in[1];
    const float* freq  = (const float*)d_in[2];
    float* y = (float*)d_out;

    k_setup<<<1, DD>>>(decay, freq);
    k_scan<<<dim3(CC, BB), NTH>>>(x, y);
}

// round 14
// speedup vs baseline: 2.9817x; 1.4532x over previous
#include <cuda_runtime.h>
#include <cuda_bf16.h>
#include <math.h>

// Problem shape (fixed by reference setup_inputs)
#define BB 4
#define TT 8192
#define DD 1024
#define LL 32             // timesteps per chunk
#define CC 256            // chunks per sequence (LL*CC == TT)
#define VEC 4             // d-columns per thread in bulk kernels
#define NTH (DD / VEC)    // 256 threads per bulk block
#define NSTEP 8           // log2(CC) Kogge-Stone steps

// kernel-2 tiling: each block scans CC chunks for DT d-columns
#define DT 4              // d-columns per scan block
#define K2_NTH (CC * DT)  // 1024 threads

// setup parallelization: 32 blocks x 32 threads (one d each) -> 32 SMs
#define SETUP_BLK 32
#define SETUP_NTH (DD / SETUP_BLK)

// Scratch (no cudaMalloc allowed -> __device__ globals)
__device__ float2 g_e[BB * CC * DD];   // chunk end states (8 MB)
__device__ float2 g_c[BB * CC * DD];   // chunk carry-in states (8 MB)
__device__ float2 g_z[DD];             // z = e^{-|a|} cis(w)
__device__ float2 g_Ap[NSTEP * DD];    // A^(2^s), A = z^LL

// streaming (evict-first) 128-bit store: y is write-once, never re-read,
// so keep it out of L2 to preserve x residency for other CTAs.
__device__ __forceinline__ void st_cs_f4(float4* p, float4 v)
{
    asm volatile("st.global.cs.v4.f32 [%0], {%1,%2,%3,%4};"
                 :: "l"(p), "f"(v.x), "f"(v.y), "f"(v.z), "f"(v.w) : "memory");
}

// ---------------------------------------------------------------------------
// Kernel 0: setup. ALL transcendentals (double precision) happen here, once
// per d — SPREAD OVER 32 BLOCKS so the ~600 FP64 ops/thread run on 32 SMs
// (R8 post-mortem: a single-block version cost ~25-36 us on one SM).
// ---------------------------------------------------------------------------
__global__ void __launch_bounds__(SETUP_NTH) k_setup(
    const float* __restrict__ decay,
    const float* __restrict__ freq)
{
    const int d = blockIdx.x * SETUP_NTH + threadIdx.x;
    const double a = fabs((double)decay[d]);
    const double w = (double)freq[d];

    const double r = exp(-a);
    g_z[d] = make_float2((float)(r * cos(w)), (float)(r * sin(w)));

    // A = z^LL in closed form, then repeated exact squaring in double
    const double rL  = exp(-a * (double)LL);
    const double phi = w * (double)LL;
    double Ar = rL * cos(phi);
    double Ai = rL * sin(phi);
#pragma unroll
    for (int s = 0; s < NSTEP; ++s) {
        g_Ap[s * DD + d] = make_float2((float)Ar, (float)Ai);
        const double nAr = Ar * Ar - Ai * Ai;
        const double nAi = 2.0 * Ar * Ai;
        Ar = nAr; Ai = nAi;
    }
}

// ---------------------------------------------------------------------------
// Kernel 1: local scan per chunk with zero initial state; store end states.
// Pure stream: read x once, write 8 MB of aggregates. No sync, no spin.
// grid = (CC, BB) = 1024 CTAs, block = 256; thread owns 4 consecutive d.
// ---------------------------------------------------------------------------
__global__ void __launch_bounds__(NTH) k_local_scan(
    const float* __restrict__ x)
{
    const int d0 = threadIdx.x * VEC;
    const int c  = blockIdx.x;
    const int b  = blockIdx.y;

    const float4 z01 = ((const float4*)(g_z + d0))[0];   // zr0,zi0,zr1,zi1
    const float4 z23 = ((const float4*)(g_z + d0))[1];
    const float zr[VEC] = {z01.x, z01.z, z23.x, z23.z};
    const float zi[VEC] = {z01.y, z01.w, z23.y, z23.w};

    float hr[VEC] = {0.f, 0.f, 0.f, 0.f};
    float hi[VEC] = {0.f, 0.f, 0.f, 0.f};

    const float4* xp = (const float4*)(x + ((size_t)b * TT + (size_t)c * LL) * DD + d0);
    const int stride4 = DD / 4;   // float4 stride per timestep

#pragma unroll 8
    for (int j = 0; j < LL; ++j) {
        const float4 xv = xp[(size_t)j * stride4];
        const float xs[VEC] = {xv.x, xv.y, xv.z, xv.w};
#pragma unroll
        for (int v = 0; v < VEC; ++v) {
            const float nr = fmaf(zr[v], hr[v], fmaf(-zi[v], hi[v], xs[v]));
            const float ni = fmaf(zi[v], hr[v], zr[v] * hi[v]);
            hr[v] = nr; hi[v] = ni;
        }
    }

    float2* ep = g_e + ((size_t)b * CC + c) * DD + d0;
    ((float4*)ep)[0] = make_float4(hr[0], hi[0], hr[1], hi[1]);
    ((float4*)ep)[1] = make_float4(hr[2], hi[2], hr[3], hi[3]);
}

// ---------------------------------------------------------------------------
// Kernel 2: Kogge-Stone scan over chunks (in smem).
// H_c = A*H_{c-1} + e_c, A = z^LL. At offset o=2^s: h_c += A^o * h_{c-o};
// A^o read from the precomputed table. Carry-in for chunk c is H_{c-1}.
// grid = (DD/DT, BB), block = 1024; tid -> (c = tid/DT, dl = tid%DT).
// Protocol per step: read s[c-o] -> sync -> write s[c] -> sync. Race-free.
// ---------------------------------------------------------------------------
__global__ void __launch_bounds__(K2_NTH) k_carry_scan()
{
    __shared__ float2 s[CC * DT];

    const int tid = threadIdx.x;
    const int dl  = tid % DT;
    const int c   = tid / DT;
    const int d   = blockIdx.x * DT + dl;
    const int b   = blockIdx.y;

    const size_t base = ((size_t)b * CC + c) * DD + d;
    float2 h = g_e[base];
    s[c * DT + dl] = h;
    __syncthreads();

    int step = 0;
#pragma unroll
    for (int o = 1; o < CC; o <<= 1, ++step) {
        const float2 A = g_Ap[step * DD + d];   // global load, barrier-independent
        float2 p = make_float2(0.0f, 0.0f);
        if (c >= o) p = s[(c - o) * DT + dl];
        __syncthreads();
        // h += A^o * p   (complex)
        h.x = fmaf(A.x, p.x, fmaf(-A.y, p.y, h.x));
        h.y = fmaf(A.y, p.x, fmaf( A.x, p.y, h.y));
        s[c * DT + dl] = h;
        __syncthreads();
    }

    // carry-in for chunk c = inclusive prefix of chunk c-1
    float2 carry = (c == 0) ? make_float2(0.0f, 0.0f) : s[(c - 1) * DT + dl];
    g_c[base] = carry;
}

// ---------------------------------------------------------------------------
// Kernel 3: final scan per chunk seeded with carry; write y = Re(h).
// Pure stream: read x + carries, write y (streaming stores — y is never
// re-read, keep it out of L2 so x stays resident for other CTAs).
// Chunk order reversed so the L2-resident tail of x is re-read first.
// grid = (CC, BB) = 1024 CTAs, block = 256; thread owns 4 consecutive d.
// ---------------------------------------------------------------------------
__global__ void __launch_bounds__(NTH) k_final_scan(
    const float* __restrict__ x,
    float* __restrict__ y)
{
    const int d0 = threadIdx.x * VEC;
    const int c  = CC - 1 - blockIdx.x;
    const int b  = blockIdx.y;

    const float4 z01 = ((const float4*)(g_z + d0))[0];
    const float4 z23 = ((const float4*)(g_z + d0))[1];
    const float zr[VEC] = {z01.x, z01.z, z23.x, z23.z};
    const float zi[VEC] = {z01.y, z01.w, z23.y, z23.w};

    float hr[VEC], hi[VEC];
    {   // seed with the carry-in state for this chunk
        const float2* cp = g_c + ((size_t)b * CC + c) * DD + d0;
        const float4 c01 = ((const float4*)cp)[0];
        const float4 c23 = ((const float4*)cp)[1];
        hr[0] = c01.x; hi[0] = c01.y; hr[1] = c01.z; hi[1] = c01.w;
        hr[2] = c23.x; hi[2] = c23.y; hr[3] = c23.z; hi[3] = c23.w;
    }

    const size_t off = ((size_t)b * TT + (size_t)c * LL) * DD + d0;
    const float4* xp = (const float4*)(x + off);
    float4*       yp = (float4*)(y + off);
    const int stride4 = DD / 4;

#pragma unroll 8
    for (int j = 0; j < LL; ++j) {
        const float4 xv = xp[(size_t)j * stride4];
        const float xs[VEC] = {xv.x, xv.y, xv.z, xv.w};
#pragma unroll
        for (int v = 0; v < VEC; ++v) {
            const float nr = fmaf(zr[v], hr[v], fmaf(-zi[v], hi[v], xs[v]));
            const float ni = fmaf(zi[v], hr[v], zr[v] * hi[v]);
            hr[v] = nr; hi[v] = ni;
        }
        st_cs_f4(yp + (size_t)j * stride4, make_float4(hr[0], hr[1], hr[2], hr[3]));
    }
}

// ---------------------------------------------------------------------------
extern "C" void kernel_launch(void* const* d_in, const int* in_sizes, int n_in,
                              void* d_out, int out_size)
{
    const float* x     = (const float*)d_in[0];
    const float* decay = (const float*)d_in[1];
    const float* freq  = (const float*)d_in[2];
    float* y = (float*)d_out;

    dim3 grid(CC, BB);
    k_setup<<<SETUP_BLK, SETUP_NTH>>>(decay, freq);
    k_local_scan<<<grid, NTH>>>(x);
    k_carry_scan<<<dim3(DD / DT, BB), K2_NTH>>>();
    k_final_scan<<<grid, NTH>>>(x, y);
}